// round 11
// baseline (speedup 1.0000x reference)
#include <cuda_runtime.h>
#include <cuda_bf16.h>
#include <stdint.h>
#include <math.h>

#define B_   2
#define S_   2048
#define H_   2048
#define NH_  16
#define NKV_ 4
#define HD_  128
#define M_   (B_*S_)
#define LOG2E 1.4426950408889634f

// ---------------- device scratch ----------------
__device__ __nv_bfloat16 hs_h[(size_t)M_*H_],      hs_l[(size_t)M_*H_];
__device__ __nv_bfloat16 wqt_h[(size_t)2048*2048], wqt_l[(size_t)2048*2048];
__device__ __nv_bfloat16 wkt_h[(size_t)512*2048],  wkt_l[(size_t)512*2048];
__device__ __nv_bfloat16 wvt_h[(size_t)512*2048],  wvt_l[(size_t)512*2048];
__device__ __nv_bfloat16 wot_h[(size_t)2048*2048], wot_l[(size_t)2048*2048];
__device__ __nv_bfloat16 g_ah[(size_t)M_*2048],    g_al[(size_t)M_*2048];
__device__ __nv_bfloat16 g_qh[(size_t)M_*2048],    g_ql[(size_t)M_*2048];
__device__ __nv_bfloat16 g_kh[(size_t)M_*512],     g_kl[(size_t)M_*512];
__device__ __nv_bfloat16 g_vh[(size_t)M_*512],     g_vl[(size_t)M_*512];
__device__ float g_tab[(size_t)64*S_*2];   // [j][pos][cos,sin]

// ---------------- PTX helpers (sm_80+ only) ----------------
__device__ __forceinline__ uint32_t smem_to_u32(const void* p) {
    uint32_t a;
    asm("{ .reg .u64 t; cvta.to.shared.u64 t, %1; cvt.u32.u64 %0, t; }"
        : "=r"(a) : "l"(p));
    return a;
}
__device__ __forceinline__ void ldsm_x4(uint32_t* r, uint32_t a) {
    asm volatile("ldmatrix.sync.aligned.m8n8.x4.shared.b16 {%0,%1,%2,%3}, [%4];"
        : "=r"(r[0]), "=r"(r[1]), "=r"(r[2]), "=r"(r[3]) : "r"(a));
}
__device__ __forceinline__ void ldsm_x2(uint32_t* r, uint32_t a) {
    asm volatile("ldmatrix.sync.aligned.m8n8.x2.shared.b16 {%0,%1}, [%2];"
        : "=r"(r[0]), "=r"(r[1]) : "r"(a));
}
__device__ __forceinline__ void ldsm_x2_t(uint32_t* r, uint32_t a) {
    asm volatile("ldmatrix.sync.aligned.m8n8.x2.trans.shared.b16 {%0,%1}, [%2];"
        : "=r"(r[0]), "=r"(r[1]) : "r"(a));
}
__device__ __forceinline__ void mma_bf16(float* c, const uint32_t* a, const uint32_t* b) {
    asm volatile("mma.sync.aligned.m16n8k16.row.col.f32.bf16.bf16.f32 "
        "{%0,%1,%2,%3}, {%4,%5,%6,%7}, {%8,%9}, {%0,%1,%2,%3};"
        : "+f"(c[0]), "+f"(c[1]), "+f"(c[2]), "+f"(c[3])
        : "r"(a[0]), "r"(a[1]), "r"(a[2]), "r"(a[3]), "r"(b[0]), "r"(b[1]));
}
#define CP16(d, s)   asm volatile("cp.async.cg.shared.global [%0], [%1], 16;" :: "r"(d), "l"(s))
#define CP_COMMIT()  asm volatile("cp.async.commit_group;" ::: "memory")
#define CP_WAIT0()   asm volatile("cp.async.wait_group 0;" ::: "memory")
#define CP_WAIT2()   asm volatile("cp.async.wait_group 2;" ::: "memory")

__device__ __forceinline__ uint32_t pack_bf16(float a, float b) {
    uint32_t lo = (uint32_t)__bfloat16_as_ushort(__float2bfloat16(a));
    uint32_t hi = (uint32_t)__bfloat16_as_ushort(__float2bfloat16(b));
    return lo | (hi << 16);
}
// split (a,b) into packed bf16 hi-pair and lo-pair
__device__ __forceinline__ void split2(float a, float b, uint32_t& h, uint32_t& l) {
    __nv_bfloat16 ah = __float2bfloat16(a), bh = __float2bfloat16(b);
    h = (uint32_t)__bfloat16_as_ushort(ah) | ((uint32_t)__bfloat16_as_ushort(bh) << 16);
    l = pack_bf16(a - __bfloat162float(ah), b - __bfloat162float(bh));
}
// 2^t for t <= 0 (clamped at -126), branch-free FMA-only
__device__ __forceinline__ float fexp2(float t) {
    t = fmaxf(t, -126.0f);
    float fi = floorf(t);
    float f = t - fi;
    float p =            1.5252734e-05f;
    p = fmaf(p, f, 1.5403530e-04f);
    p = fmaf(p, f, 1.3333558e-03f);
    p = fmaf(p, f, 9.6181291e-03f);
    p = fmaf(p, f, 5.5504109e-02f);
    p = fmaf(p, f, 2.4022651e-01f);
    p = fmaf(p, f, 6.9314718e-01f);
    p = fmaf(p, f, 1.0f);
    return __int_as_float(__float_as_int(p) + (__float2int_rn(fi) << 23));
}

// ---------------- prep kernels ----------------
__global__ void split_hs_kernel(const float* __restrict__ hs)
{
    const size_t n4 = (size_t)M_ * H_ / 4;
    for (size_t i = blockIdx.x * (size_t)blockDim.x + threadIdx.x; i < n4;
         i += (size_t)gridDim.x * blockDim.x) {
        float4 v = ((const float4*)hs)[i];
        float x[4] = {v.x, v.y, v.z, v.w};
        #pragma unroll
        for (int c = 0; c < 4; c++) {
            __nv_bfloat16 hi = __float2bfloat16(x[c]);
            hs_h[i*4 + c] = hi;
            hs_l[i*4 + c] = __float2bfloat16(x[c] - __bfloat162float(hi));
        }
    }
}

// W[K][N] row-major -> T_hi/T_lo[N][K] bf16
__global__ void wsplit_kernel(const float* __restrict__ W, int K, int N, int sel)
{
    __nv_bfloat16 *Th, *Tl;
    if (sel == 0)      { Th = wqt_h; Tl = wqt_l; }
    else if (sel == 1) { Th = wkt_h; Tl = wkt_l; }
    else if (sel == 2) { Th = wvt_h; Tl = wvt_l; }
    else               { Th = wot_h; Tl = wot_l; }
    __shared__ float ts[32][33];
    int n0 = blockIdx.x * 32, k0 = blockIdx.y * 32;
    int tx = threadIdx.x, ty = threadIdx.y;
    #pragma unroll
    for (int i = 0; i < 4; i++)
        ts[ty + i*8][tx] = W[(size_t)(k0 + ty + i*8) * N + n0 + tx];
    __syncthreads();
    #pragma unroll
    for (int i = 0; i < 4; i++) {
        float x = ts[tx][ty + i*8];
        __nv_bfloat16 hi = __float2bfloat16(x);
        size_t o = (size_t)(n0 + ty + i*8) * K + k0 + tx;
        Th[o] = hi;
        Tl[o] = __float2bfloat16(x - __bfloat162float(hi));
    }
}

__global__ void rope_table_kernel()
{
    int idx = blockIdx.x * blockDim.x + threadIdx.x;
    if (idx >= S_ * 64) return;
    int j = idx >> 11, pos = idx & (S_ - 1);
    double ang = (double)pos * pow(10000.0, -(double)(2 * j) / 128.0);
    g_tab[idx*2]     = (float)cos(ang);
    g_tab[idx*2 + 1] = (float)sin(ang);
}

// ---------------------------------------------------------------------------
// Split-bf16 GEMM (mma.sync m16n8k16). C = A @ W; 3 passes AhBh+AhBl+AlBh.
// CTA 128x128, BK=32, 8 warps 64x32.
// 4-stage cp.async ring, ONE __syncthreads per chunk:
//   iter kt: wait_group 2 -> sync -> issue loads for chunk kt+3 -> compute kt.
// Unconditional commit keeps group accounting exact in the tail.
// mode: 0 -> f32 Cout, 1 rope->g_qh/l, 2 rope->g_kh/l, 3 -> g_vh/l.
// ---------------------------------------------------------------------------
#define TPAD    40
#define TILEB   10240u
#define BUFB    (4u*TILEB)
#define MM_SMEM (4u*BUFB)   // 163,840 B (4 stages)

__device__ __forceinline__ void compute_chunk(uint32_t tb, float (*acc)[4][4],
                                              int lane, int wm, int wn)
{
    #pragma unroll
    for (int ks = 0; ks < 2; ks++) {
        const int k0 = ks * 16;
        uint32_t ah[4][4], al[4][4], bh[4][2], bl[4][2];
        const int arow = wm*64 + (lane & 15);
        const int acol = k0 + (lane >> 4) * 8;
        #pragma unroll
        for (int ma = 0; ma < 4; ma++) {
            uint32_t off = (uint32_t)(((arow + ma*16)*TPAD + acol) * 2);
            ldsm_x4(ah[ma], tb + off);
            ldsm_x4(al[ma], tb + TILEB + off);
        }
        const int bl8 = lane & 15;
        #pragma unroll
        for (int na = 0; na < 4; na++) {
            int nc = wn*16 + (na&1)*8 + (na>>1)*64 + (bl8 & 7);
            uint32_t off = (uint32_t)((nc*TPAD + k0 + (bl8 >> 3)*8) * 2);
            ldsm_x2(bh[na], tb + 2*TILEB + off);
            ldsm_x2(bl[na], tb + 3*TILEB + off);
        }
        #pragma unroll
        for (int ma = 0; ma < 4; ma++)
            #pragma unroll
            for (int na = 0; na < 4; na++) {
                mma_bf16(acc[ma][na], ah[ma], bh[na]);
                mma_bf16(acc[ma][na], ah[ma], bl[na]);
                mma_bf16(acc[ma][na], al[ma], bh[na]);
            }
    }
}

__global__ __launch_bounds__(256) void mm_mma(
    float* __restrict__ Cout, int K, int asel, int bsel, int mode, int ncols)
{
    extern __shared__ char dsm[];
    const uint32_t sbase = smem_to_u32(dsm);
    const int t = threadIdx.x, lane = t & 31, wid = t >> 5;
    const int wm = wid >> 2, wn = wid & 3;
    const int bn = blockIdx.x * 128, bm = blockIdx.y * 128;

    const __nv_bfloat16 *Ah, *Al, *Bh, *Bl;
    if (asel == 0) { Ah = hs_h; Al = hs_l; } else { Ah = g_ah; Al = g_al; }
    if (bsel == 0)      { Bh = wqt_h; Bl = wqt_l; }
    else if (bsel == 1) { Bh = wkt_h; Bl = wkt_l; }
    else if (bsel == 2) { Bh = wvt_h; Bl = wvt_l; }
    else                { Bh = wot_h; Bl = wot_l; }

    float acc[4][4][4];
    #pragma unroll
    for (int a = 0; a < 4; a++)
        #pragma unroll
        for (int b = 0; b < 4; b++)
            #pragma unroll
            for (int c = 0; c < 4; c++) acc[a][b][c] = 0.f;

    const int NK = K >> 5;

#define LOADT(SRC, RB, TOFF) \
    _Pragma("unroll") \
    for (int i = 0; i < 2; i++) { \
        int idx = t + i*256; \
        int row = idx >> 2, cc = idx & 3; \
        uint32_t dst = sbase + buf + (TOFF) + (uint32_t)((row*TPAD + cc*8)*2); \
        const void* src = (SRC) + (size_t)((RB) + row)*K + k0 + cc*8; \
        CP16(dst, src); \
    }
#define LOADCHUNK(CIDX) do { \
        const int k0 = (CIDX) << 5; \
        const uint32_t buf = (uint32_t)((CIDX) & 3) * BUFB; \
        LOADT(Ah, bm, 0) LOADT(Al, bm, TILEB) \
        LOADT(Bh, bn, 2*TILEB) LOADT(Bl, bn, 3*TILEB) \
    } while (0)

    // prologue: chunks 0,1,2 in flight (NK = 64 here, always > 3)
    LOADCHUNK(0); CP_COMMIT();
    LOADCHUNK(1); CP_COMMIT();
    LOADCHUNK(2); CP_COMMIT();

    for (int kt = 0; kt < NK; kt++) {
        CP_WAIT2();                 // chunk kt resident (<=2 younger groups pending)
        __syncthreads();            // visibility + bounds skew to one iteration
        if (kt + 3 < NK) LOADCHUNK(kt + 3);
        CP_COMMIT();                // unconditional: keeps group accounting exact
        compute_chunk(sbase + (uint32_t)(kt & 3) * BUFB, acc, lane, wm, wn);
    }
#undef LOADCHUNK
#undef LOADT

    // ---- epilogue ----
    if (mode == 0) {
        #pragma unroll
        for (int ma = 0; ma < 4; ma++) {
            int r0 = bm + wm*64 + ma*16 + (lane >> 2);
            #pragma unroll
            for (int na = 0; na < 4; na++) {
                int col = bn + wn*16 + (na&1)*8 + (na>>1)*64 + 2*(lane & 3);
                *(float2*)(Cout + (size_t)r0*ncols + col)     = make_float2(acc[ma][na][0], acc[ma][na][1]);
                *(float2*)(Cout + (size_t)(r0+8)*ncols + col) = make_float2(acc[ma][na][2], acc[ma][na][3]);
            }
        }
    } else if (mode == 3) {
        #pragma unroll
        for (int ma = 0; ma < 4; ma++) {
            int r0 = bm + wm*64 + ma*16 + (lane >> 2);
            #pragma unroll
            for (int na = 0; na < 4; na++) {
                int col = bn + wn*16 + (na&1)*8 + (na>>1)*64 + 2*(lane & 3);
                uint32_t h0, l0, h1, l1;
                split2(acc[ma][na][0], acc[ma][na][1], h0, l0);
                split2(acc[ma][na][2], acc[ma][na][3], h1, l1);
                *(uint32_t*)&g_vh[(size_t)r0*ncols + col]     = h0;
                *(uint32_t*)&g_vl[(size_t)r0*ncols + col]     = l0;
                *(uint32_t*)&g_vh[(size_t)(r0+8)*ncols + col] = h1;
                *(uint32_t*)&g_vl[(size_t)(r0+8)*ncols + col] = l1;
            }
        }
    } else {
        __nv_bfloat16* dh = (mode == 1) ? g_qh : g_kh;
        __nv_bfloat16* dl = (mode == 1) ? g_ql : g_kl;
        #pragma unroll
        for (int ma = 0; ma < 4; ma++) {
            int r0 = bm + wm*64 + ma*16 + (lane >> 2);
            #pragma unroll
            for (int na = 0; na < 2; na++) {
                int jb = wn*16 + na*8 + 2*(lane & 3);
                #pragma unroll
                for (int half = 0; half < 2; half++) {
                    int r = r0 + half*8;
                    int spos = r & (S_ - 1);
                    float c0 = g_tab[((size_t)jb*S_ + spos)*2];
                    float s0 = g_tab[((size_t)jb*S_ + spos)*2 + 1];
                    float c1 = g_tab[((size_t)(jb+1)*S_ + spos)*2];
                    float s1 = g_tab[((size_t)(jb+1)*S_ + spos)*2 + 1];
                    float x1a = acc[ma][na][half*2+0],   x1b = acc[ma][na][half*2+1];
                    float x2a = acc[ma][na+2][half*2+0], x2b = acc[ma][na+2][half*2+1];
                    float y0 = x1a*c0 - x2a*s0, y1 = x1b*c1 - x2b*s1;   // cols jb, jb+1
                    float z0 = x2a*c0 + x1a*s0, z1 = x2b*c1 + x1b*s1;   // cols jb+64, jb+65
                    uint32_t h0, l0, h1, l1;
                    split2(y0, y1, h0, l0);
                    split2(z0, z1, h1, l1);
                    size_t p = (size_t)r*ncols + bn + jb;
                    *(uint32_t*)&dh[p]      = h0;
                    *(uint32_t*)&dl[p]      = l0;
                    *(uint32_t*)&dh[p + 64] = h1;
                    *(uint32_t*)&dl[p + 64] = l1;
                }
            }
        }
    }
}

// ---------------------------------------------------------------------------
// Flash attention on mma.sync, split-bf16 both GEMMs, register softmax.
// 256 threads / 8 warps; warp w owns query rows [w*16, w*16+16).
// (unchanged from R10 — isolates the GEMM pipeline change)
// ---------------------------------------------------------------------------
#define QSTR 136
#define PSTR 72
#define QH_OFF 0u
#define QL_OFF 34816u
#define KH_OFF 69632u
#define KL_OFF 87040u
#define VH_OFF 104448u
#define VL_OFF 121856u
#define PH_OFF 139264u
#define PL_OFF 157696u
#define ATT_SMEM 176128u

__global__ __launch_bounds__(256) void attn_mma()
{
    extern __shared__ char dsm[];
    const uint32_t sb = smem_to_u32(dsm);
    const int t = threadIdx.x, lane = t & 31, wid = t >> 5;
    const int qt = 15 - blockIdx.x;          // heavy q-tiles first
    const int h = blockIdx.y, b = blockIdx.z;
    const int kvh = h >> 2;
    const int qbase = qt * 128;
    const int r_in = lane >> 2;              // 0..7
    const int c2 = (lane & 3) * 2;

    // load Q tile (hi+lo)
    {
        const __nv_bfloat16* qh = g_qh + (size_t)(b*S_ + qbase)*2048 + h*128;
        const __nv_bfloat16* ql = g_ql + (size_t)(b*S_ + qbase)*2048 + h*128;
        for (int i = t; i < 2048; i += 256) {
            int r = i >> 4, c = (i & 15) * 8;
            uint32_t d = sb + QH_OFF + (uint32_t)((r*QSTR + c)*2);
            CP16(d, qh + (size_t)r*2048 + c);
            CP16(d + QL_OFF, ql + (size_t)r*2048 + c);
        }
        CP_COMMIT();
    }

    float o[16][4];
    #pragma unroll
    for (int i = 0; i < 16; i++)
        #pragma unroll
        for (int e = 0; e < 4; e++) o[i][e] = 0.f;
    float m_run[2] = {-1e30f, -1e30f}, l_run[2] = {0.f, 0.f};

    const float scale = 0.08838834764831845f;
    const int ntiles = 2*qt + 2;
    for (int kt = 0; kt < ntiles; kt++) {
        const int kbase = kt * 64;
        __syncthreads();   // all warps done reading prev K/V
        for (int i = t; i < 1024; i += 256) {
            int r = i >> 4, c = (i & 15) * 8;
            uint32_t doff = (uint32_t)((r*QSTR + c)*2);
            size_t goff = (size_t)(b*S_ + kbase + r)*512 + kvh*128 + c;
            CP16(sb + KH_OFF + doff, g_kh + goff);
            CP16(sb + KL_OFF + doff, g_kl + goff);
            CP16(sb + VH_OFF + doff, g_vh + goff);
            CP16(sb + VL_OFF + doff, g_vl + goff);
        }
        CP_COMMIT();
        CP_WAIT0();
        __syncthreads();

        // ---- S = Q K^T (3-pass split) ----
        float s[8][4];
        #pragma unroll
        for (int na = 0; na < 8; na++)
            #pragma unroll
            for (int e = 0; e < 4; e++) s[na][e] = 0.f;
        #pragma unroll
        for (int ks = 0; ks < 8; ks++) {
            const int k0 = ks * 16;
            uint32_t ah[4], al[4];
            uint32_t aoff = sb + QH_OFF +
                (uint32_t)(((wid*16 + (lane & 15))*QSTR + k0 + (lane >> 4)*8)*2);
            ldsm_x4(ah, aoff);
            ldsm_x4(al, aoff + (QL_OFF - QH_OFF));
            #pragma unroll
            for (int na = 0; na < 8; na++) {
                uint32_t bh[2], bl[2];
                uint32_t boff = sb + KH_OFF +
                    (uint32_t)(((na*8 + (lane & 7))*QSTR + k0 + ((lane >> 3) & 1)*8)*2);
                ldsm_x2(bh, boff);
                ldsm_x2(bl, boff + (KL_OFF - KH_OFF));
                mma_bf16(s[na], ah, bh);
                mma_bf16(s[na], ah, bl);
                mma_bf16(s[na], al, bh);
            }
        }
        // scale + causal mask
        const bool mm = (kt >= 2*qt);
        #pragma unroll
        for (int na = 0; na < 8; na++)
            #pragma unroll
            for (int e = 0; e < 4; e++) {
                float v = s[na][e] * scale;
                if (mm) {
                    int col = kbase + na*8 + c2 + (e & 1);
                    int row = qbase + wid*16 + r_in + (e >> 1)*8;
                    if (col > row) v = -1e30f;
                }
                s[na][e] = v;
            }
        // row max (2 rows per lane)
        float mt[2] = {-1e30f, -1e30f};
        #pragma unroll
        for (int na = 0; na < 8; na++) {
            mt[0] = fmaxf(mt[0], fmaxf(s[na][0], s[na][1]));
            mt[1] = fmaxf(mt[1], fmaxf(s[na][2], s[na][3]));
        }
        #pragma unroll
        for (int x = 1; x < 4; x <<= 1) {
            mt[0] = fmaxf(mt[0], __shfl_xor_sync(0xFFFFFFFFu, mt[0], x));
            mt[1] = fmaxf(mt[1], __shfl_xor_sync(0xFFFFFFFFu, mt[1], x));
        }
        float mn0 = fmaxf(m_run[0], mt[0]), mn1 = fmaxf(m_run[1], mt[1]);
        float al0 = fexp2((m_run[0] - mn0) * LOG2E);
        float al1 = fexp2((m_run[1] - mn1) * LOG2E);
        m_run[0] = mn0; m_run[1] = mn1;

        // p = exp(s - m), row sums, store P (hi/lo) to this warp's smem rows
        float rs0 = 0.f, rs1 = 0.f;
        uint32_t pbase = sb + PH_OFF +
            (uint32_t)(((wid*16 + r_in)*PSTR + c2)*2);
        #pragma unroll
        for (int na = 0; na < 8; na++) {
            float p0 = fexp2((s[na][0] - mn0) * LOG2E);
            float p1 = fexp2((s[na][1] - mn0) * LOG2E);
            float p2 = fexp2((s[na][2] - mn1) * LOG2E);
            float p3 = fexp2((s[na][3] - mn1) * LOG2E);
            rs0 += p0 + p1; rs1 += p2 + p3;
            uint32_t h0, l0, h1, l1;
            split2(p0, p1, h0, l0);
            split2(p2, p3, h1, l1);
            uint32_t a0 = pbase + (uint32_t)(na*8*2);
            uint32_t a1 = a0 + (uint32_t)(8*PSTR*2);
            *(uint32_t*)(dsm + (a0 - sb))                    = h0;
            *(uint32_t*)(dsm + (a0 - sb) + (PL_OFF - PH_OFF)) = l0;
            *(uint32_t*)(dsm + (a1 - sb))                    = h1;
            *(uint32_t*)(dsm + (a1 - sb) + (PL_OFF - PH_OFF)) = l1;
        }
        #pragma unroll
        for (int x = 1; x < 4; x <<= 1) {
            rs0 += __shfl_xor_sync(0xFFFFFFFFu, rs0, x);
            rs1 += __shfl_xor_sync(0xFFFFFFFFu, rs1, x);
        }
        l_run[0] = l_run[0]*al0 + rs0;
        l_run[1] = l_run[1]*al1 + rs1;
        // rescale O
        #pragma unroll
        for (int nd = 0; nd < 16; nd++) {
            o[nd][0] *= al0; o[nd][1] *= al0;
            o[nd][2] *= al1; o[nd][3] *= al1;
        }
        __syncwarp();

        // ---- O += P V (3-pass split), V fragments via ldmatrix.trans ----
        #pragma unroll
        for (int kk = 0; kk < 4; kk++) {
            const int k0 = kk * 16;
            uint32_t ph4[4], pl4[4];
            uint32_t poff = sb + PH_OFF +
                (uint32_t)(((wid*16 + (lane & 15))*PSTR + k0 + (lane >> 4)*8)*2);
            ldsm_x4(ph4, poff);
            ldsm_x4(pl4, poff + (PL_OFF - PH_OFF));
            #pragma unroll
            for (int nd = 0; nd < 16; nd++) {
                uint32_t bh[2], bl[2];
                uint32_t voff = sb + VH_OFF +
                    (uint32_t)(((k0 + (lane & 15))*QSTR + nd*8)*2);
                ldsm_x2_t(bh, voff);
                ldsm_x2_t(bl, voff + (VL_OFF - VH_OFF));
                mma_bf16(o[nd], ph4, bh);
                mma_bf16(o[nd], pl4, bh);
                mma_bf16(o[nd], ph4, bl);
            }
        }
    }

    // ---- epilogue: /= l, emit bf16 hi/lo for out-proj ----
    float inv0 = 1.f / l_run[0], inv1 = 1.f / l_run[1];
    int row0 = b*S_ + qbase + wid*16 + r_in;
    #pragma unroll
    for (int nd = 0; nd < 16; nd++) {
        int d = nd*8 + c2;
        uint32_t h0, l0, h1, l1;
        split2(o[nd][0]*inv0, o[nd][1]*inv0, h0, l0);
        split2(o[nd][2]*inv1, o[nd][3]*inv1, h1, l1);
        size_t p0 = (size_t)row0*2048 + h*128 + d;
        size_t p1 = p0 + (size_t)8*2048;
        *(uint32_t*)&g_ah[p0] = h0;
        *(uint32_t*)&g_al[p0] = l0;
        *(uint32_t*)&g_ah[p1] = h1;
        *(uint32_t*)&g_al[p1] = l1;
    }
}

// ---------------------------------------------------------------------------
// Launch.  Inputs: hidden_states f32, position_ids (arange, unused),
//                  Wq, Wk, Wv, Wo f32.  Output f32 [B,S,H].
// ---------------------------------------------------------------------------
extern "C" void kernel_launch(void* const* d_in, const int* in_sizes, int n_in,
                              void* d_out, int out_size)
{
    (void)in_sizes; (void)n_in; (void)out_size;
    const float* hs = (const float*)d_in[0];
    const float* Wq = (const float*)d_in[2];
    const float* Wk = (const float*)d_in[3];
    const float* Wv = (const float*)d_in[4];
    const float* Wo = (const float*)d_in[5];
    float* out = (float*)d_out;

    cudaFuncSetAttribute(mm_mma, cudaFuncAttributeMaxDynamicSharedMemorySize, MM_SMEM);
    cudaFuncSetAttribute(attn_mma, cudaFuncAttributeMaxDynamicSharedMemorySize, ATT_SMEM);

    // prep
    split_hs_kernel<<<1024, 256>>>(hs);
    wsplit_kernel<<<dim3(2048/32, 2048/32), dim3(32, 8)>>>(Wq, 2048, 2048, 0);
    wsplit_kernel<<<dim3(512/32,  2048/32), dim3(32, 8)>>>(Wk, 2048, 512,  1);
    wsplit_kernel<<<dim3(512/32,  2048/32), dim3(32, 8)>>>(Wv, 2048, 512,  2);
    wsplit_kernel<<<dim3(2048/32, 2048/32), dim3(32, 8)>>>(Wo, 2048, 2048, 3);
    rope_table_kernel<<<(S_*64 + 255)/256, 256>>>();

    // projections (RoPE fused for Q/K; all emit bf16 hi/lo)
    mm_mma<<<dim3(16, 32), 256, MM_SMEM>>>(nullptr, 2048, 0, 0, 1, 2048);
    mm_mma<<<dim3(4,  32), 256, MM_SMEM>>>(nullptr, 2048, 0, 1, 2, 512);
    mm_mma<<<dim3(4,  32), 256, MM_SMEM>>>(nullptr, 2048, 0, 2, 3, 512);

    // attention (tensor-core, split-bf16)
    attn_mma<<<dim3(16, NH_, B_), 256, ATT_SMEM>>>();

    // output projection
    mm_mma<<<dim3(16, 32), 256, MM_SMEM>>>(out, 2048, 1, 3, 0, 2048);
}

// round 12
// speedup vs baseline: 1.1189x; 1.1189x over previous
#include <cuda_runtime.h>
#include <cuda_bf16.h>
#include <stdint.h>
#include <math.h>

#define B_   2
#define S_   2048
#define H_   2048
#define NH_  16
#define NKV_ 4
#define HD_  128
#define M_   (B_*S_)
#define LOG2E 1.4426950408889634f

// ---------------- device scratch ----------------
__device__ __nv_bfloat16 hs_h[(size_t)M_*H_],      hs_l[(size_t)M_*H_];
__device__ __nv_bfloat16 wqt_h[(size_t)2048*2048], wqt_l[(size_t)2048*2048];
__device__ __nv_bfloat16 wkt_h[(size_t)512*2048],  wkt_l[(size_t)512*2048];
__device__ __nv_bfloat16 wvt_h[(size_t)512*2048],  wvt_l[(size_t)512*2048];
__device__ __nv_bfloat16 wot_h[(size_t)2048*2048], wot_l[(size_t)2048*2048];
__device__ __nv_bfloat16 g_ah[(size_t)M_*2048],    g_al[(size_t)M_*2048];
__device__ __nv_bfloat16 g_qh[(size_t)M_*2048],    g_ql[(size_t)M_*2048];
__device__ __nv_bfloat16 g_kh[(size_t)M_*512],     g_kl[(size_t)M_*512];
__device__ __nv_bfloat16 g_vh[(size_t)M_*512],     g_vl[(size_t)M_*512];
__device__ float g_tab[(size_t)64*S_*2];   // [j][pos][cos,sin]

// ---------------- PTX helpers (sm_80+ only) ----------------
__device__ __forceinline__ uint32_t smem_to_u32(const void* p) {
    uint32_t a;
    asm("{ .reg .u64 t; cvta.to.shared.u64 t, %1; cvt.u32.u64 %0, t; }"
        : "=r"(a) : "l"(p));
    return a;
}
__device__ __forceinline__ void ldsm_x4(uint32_t* r, uint32_t a) {
    asm volatile("ldmatrix.sync.aligned.m8n8.x4.shared.b16 {%0,%1,%2,%3}, [%4];"
        : "=r"(r[0]), "=r"(r[1]), "=r"(r[2]), "=r"(r[3]) : "r"(a));
}
__device__ __forceinline__ void ldsm_x2(uint32_t* r, uint32_t a) {
    asm volatile("ldmatrix.sync.aligned.m8n8.x2.shared.b16 {%0,%1}, [%2];"
        : "=r"(r[0]), "=r"(r[1]) : "r"(a));
}
__device__ __forceinline__ void ldsm_x2_t(uint32_t* r, uint32_t a) {
    asm volatile("ldmatrix.sync.aligned.m8n8.x2.trans.shared.b16 {%0,%1}, [%2];"
        : "=r"(r[0]), "=r"(r[1]) : "r"(a));
}
__device__ __forceinline__ void mma_bf16(float* c, const uint32_t* a, const uint32_t* b) {
    asm volatile("mma.sync.aligned.m16n8k16.row.col.f32.bf16.bf16.f32 "
        "{%0,%1,%2,%3}, {%4,%5,%6,%7}, {%8,%9}, {%0,%1,%2,%3};"
        : "+f"(c[0]), "+f"(c[1]), "+f"(c[2]), "+f"(c[3])
        : "r"(a[0]), "r"(a[1]), "r"(a[2]), "r"(a[3]), "r"(b[0]), "r"(b[1]));
}
#define CP16(d, s)   asm volatile("cp.async.cg.shared.global [%0], [%1], 16;" :: "r"(d), "l"(s))
#define CP_COMMIT()  asm volatile("cp.async.commit_group;" ::: "memory")
#define CP_WAIT0()   asm volatile("cp.async.wait_group 0;" ::: "memory")
#define CP_WAIT1()   asm volatile("cp.async.wait_group 1;" ::: "memory")

__device__ __forceinline__ uint32_t pack_bf16(float a, float b) {
    uint32_t lo = (uint32_t)__bfloat16_as_ushort(__float2bfloat16(a));
    uint32_t hi = (uint32_t)__bfloat16_as_ushort(__float2bfloat16(b));
    return lo | (hi << 16);
}
// split (a,b) into packed bf16 hi-pair and lo-pair
__device__ __forceinline__ void split2(float a, float b, uint32_t& h, uint32_t& l) {
    __nv_bfloat16 ah = __float2bfloat16(a), bh = __float2bfloat16(b);
    h = (uint32_t)__bfloat16_as_ushort(ah) | ((uint32_t)__bfloat16_as_ushort(bh) << 16);
    l = pack_bf16(a - __bfloat162float(ah), b - __bfloat162float(bh));
}
// 2^t for t <= 0 (clamped at -126), branch-free FMA-only
__device__ __forceinline__ float fexp2(float t) {
    t = fmaxf(t, -126.0f);
    float fi = floorf(t);
    float f = t - fi;
    float p =            1.5252734e-05f;
    p = fmaf(p, f, 1.5403530e-04f);
    p = fmaf(p, f, 1.3333558e-03f);
    p = fmaf(p, f, 9.6181291e-03f);
    p = fmaf(p, f, 5.5504109e-02f);
    p = fmaf(p, f, 2.4022651e-01f);
    p = fmaf(p, f, 6.9314718e-01f);
    p = fmaf(p, f, 1.0f);
    return __int_as_float(__float_as_int(p) + (__float2int_rn(fi) << 23));
}

// ---------------- prep kernels ----------------
__global__ void split_hs_kernel(const float* __restrict__ hs)
{
    const size_t n4 = (size_t)M_ * H_ / 4;
    for (size_t i = blockIdx.x * (size_t)blockDim.x + threadIdx.x; i < n4;
         i += (size_t)gridDim.x * blockDim.x) {
        float4 v = ((const float4*)hs)[i];
        float x[4] = {v.x, v.y, v.z, v.w};
        #pragma unroll
        for (int c = 0; c < 4; c++) {
            __nv_bfloat16 hi = __float2bfloat16(x[c]);
            hs_h[i*4 + c] = hi;
            hs_l[i*4 + c] = __float2bfloat16(x[c] - __bfloat162float(hi));
        }
    }
}

// W[K][N] row-major -> T_hi/T_lo[N][K] bf16
__global__ void wsplit_kernel(const float* __restrict__ W, int K, int N, int sel)
{
    __nv_bfloat16 *Th, *Tl;
    if (sel == 0)      { Th = wqt_h; Tl = wqt_l; }
    else if (sel == 1) { Th = wkt_h; Tl = wkt_l; }
    else if (sel == 2) { Th = wvt_h; Tl = wvt_l; }
    else               { Th = wot_h; Tl = wot_l; }
    __shared__ float ts[32][33];
    int n0 = blockIdx.x * 32, k0 = blockIdx.y * 32;
    int tx = threadIdx.x, ty = threadIdx.y;
    #pragma unroll
    for (int i = 0; i < 4; i++)
        ts[ty + i*8][tx] = W[(size_t)(k0 + ty + i*8) * N + n0 + tx];
    __syncthreads();
    #pragma unroll
    for (int i = 0; i < 4; i++) {
        float x = ts[tx][ty + i*8];
        __nv_bfloat16 hi = __float2bfloat16(x);
        size_t o = (size_t)(n0 + ty + i*8) * K + k0 + tx;
        Th[o] = hi;
        Tl[o] = __float2bfloat16(x - __bfloat162float(hi));
    }
}

__global__ void rope_table_kernel()
{
    int idx = blockIdx.x * blockDim.x + threadIdx.x;
    if (idx >= S_ * 64) return;
    int j = idx >> 11, pos = idx & (S_ - 1);
    double ang = (double)pos * pow(10000.0, -(double)(2 * j) / 128.0);
    g_tab[idx*2]     = (float)cos(ang);
    g_tab[idx*2 + 1] = (float)sin(ang);
}

// ---------------------------------------------------------------------------
// Split-bf16 GEMM (mma.sync m16n8k16). C = A @ W; 3 passes AhBh+AhBl+AlBh.
// CTA 128x128, BK=32, 8 warps 64x32, cp.async double buffer.
// (R10-proven version: 2 stages, 80KB smem -> 2 CTAs/SM.)
// mode: 0 -> f32 Cout, 1 rope->g_qh/l, 2 rope->g_kh/l, 3 -> g_vh/l.
// ---------------------------------------------------------------------------
#define TPAD    40
#define TILEB   10240u
#define BUFB    (4u*TILEB)
#define MM_SMEM (2u*BUFB)   // 81,920 B

__device__ __forceinline__ void compute_chunk(uint32_t tb, float (*acc)[4][4],
                                              int lane, int wm, int wn)
{
    #pragma unroll
    for (int ks = 0; ks < 2; ks++) {
        const int k0 = ks * 16;
        uint32_t ah[4][4], al[4][4], bh[4][2], bl[4][2];
        const int arow = wm*64 + (lane & 15);
        const int acol = k0 + (lane >> 4) * 8;
        #pragma unroll
        for (int ma = 0; ma < 4; ma++) {
            uint32_t off = (uint32_t)(((arow + ma*16)*TPAD + acol) * 2);
            ldsm_x4(ah[ma], tb + off);
            ldsm_x4(al[ma], tb + TILEB + off);
        }
        const int bl8 = lane & 15;
        #pragma unroll
        for (int na = 0; na < 4; na++) {
            int nc = wn*16 + (na&1)*8 + (na>>1)*64 + (bl8 & 7);
            uint32_t off = (uint32_t)((nc*TPAD + k0 + (bl8 >> 3)*8) * 2);
            ldsm_x2(bh[na], tb + 2*TILEB + off);
            ldsm_x2(bl[na], tb + 3*TILEB + off);
        }
        #pragma unroll
        for (int ma = 0; ma < 4; ma++)
            #pragma unroll
            for (int na = 0; na < 4; na++) {
                mma_bf16(acc[ma][na], ah[ma], bh[na]);
                mma_bf16(acc[ma][na], ah[ma], bl[na]);
                mma_bf16(acc[ma][na], al[ma], bh[na]);
            }
    }
}

__global__ __launch_bounds__(256) void mm_mma(
    float* __restrict__ Cout, int K, int asel, int bsel, int mode, int ncols)
{
    extern __shared__ char dsm[];
    const uint32_t sbase = smem_to_u32(dsm);
    const int t = threadIdx.x, lane = t & 31, wid = t >> 5;
    const int wm = wid >> 2, wn = wid & 3;
    const int bn = blockIdx.x * 128, bm = blockIdx.y * 128;

    const __nv_bfloat16 *Ah, *Al, *Bh, *Bl;
    if (asel == 0) { Ah = hs_h; Al = hs_l; } else { Ah = g_ah; Al = g_al; }
    if (bsel == 0)      { Bh = wqt_h; Bl = wqt_l; }
    else if (bsel == 1) { Bh = wkt_h; Bl = wkt_l; }
    else if (bsel == 2) { Bh = wvt_h; Bl = wvt_l; }
    else                { Bh = wot_h; Bl = wot_l; }

    float acc[4][4][4];
    #pragma unroll
    for (int a = 0; a < 4; a++)
        #pragma unroll
        for (int b = 0; b < 4; b++)
            #pragma unroll
            for (int c = 0; c < 4; c++) acc[a][b][c] = 0.f;

    const int NK = K >> 5;

#define LOADT(SRC, RB, TOFF) \
    _Pragma("unroll") \
    for (int i = 0; i < 2; i++) { \
        int idx = t + i*256; \
        int row = idx >> 2, cc = idx & 3; \
        uint32_t dst = sbase + buf + (TOFF) + (uint32_t)((row*TPAD + cc*8)*2); \
        const void* src = (SRC) + (size_t)((RB) + row)*K + k0 + cc*8; \
        CP16(dst, src); \
    }

    {
        const int k0 = 0; const uint32_t buf = 0;
        LOADT(Ah, bm, 0) LOADT(Al, bm, TILEB)
        LOADT(Bh, bn, 2*TILEB) LOADT(Bl, bn, 3*TILEB)
        CP_COMMIT();
    }
    for (int kt = 0; kt < NK; kt++) {
        if (kt + 1 < NK) {
            const int k0 = (kt + 1) << 5;
            const uint32_t buf = (uint32_t)((kt + 1) & 1) * BUFB;
            LOADT(Ah, bm, 0) LOADT(Al, bm, TILEB)
            LOADT(Bh, bn, 2*TILEB) LOADT(Bl, bn, 3*TILEB)
            CP_COMMIT();
            CP_WAIT1();
        } else {
            CP_WAIT0();
        }
        __syncthreads();
        compute_chunk(sbase + (uint32_t)(kt & 1) * BUFB, acc, lane, wm, wn);
        __syncthreads();
    }
#undef LOADT

    // ---- epilogue ----
    if (mode == 0) {
        #pragma unroll
        for (int ma = 0; ma < 4; ma++) {
            int r0 = bm + wm*64 + ma*16 + (lane >> 2);
            #pragma unroll
            for (int na = 0; na < 4; na++) {
                int col = bn + wn*16 + (na&1)*8 + (na>>1)*64 + 2*(lane & 3);
                *(float2*)(Cout + (size_t)r0*ncols + col)     = make_float2(acc[ma][na][0], acc[ma][na][1]);
                *(float2*)(Cout + (size_t)(r0+8)*ncols + col) = make_float2(acc[ma][na][2], acc[ma][na][3]);
            }
        }
    } else if (mode == 3) {
        #pragma unroll
        for (int ma = 0; ma < 4; ma++) {
            int r0 = bm + wm*64 + ma*16 + (lane >> 2);
            #pragma unroll
            for (int na = 0; na < 4; na++) {
                int col = bn + wn*16 + (na&1)*8 + (na>>1)*64 + 2*(lane & 3);
                uint32_t h0, l0, h1, l1;
                split2(acc[ma][na][0], acc[ma][na][1], h0, l0);
                split2(acc[ma][na][2], acc[ma][na][3], h1, l1);
                *(uint32_t*)&g_vh[(size_t)r0*ncols + col]     = h0;
                *(uint32_t*)&g_vl[(size_t)r0*ncols + col]     = l0;
                *(uint32_t*)&g_vh[(size_t)(r0+8)*ncols + col] = h1;
                *(uint32_t*)&g_vl[(size_t)(r0+8)*ncols + col] = l1;
            }
        }
    } else {
        __nv_bfloat16* dh = (mode == 1) ? g_qh : g_kh;
        __nv_bfloat16* dl = (mode == 1) ? g_ql : g_kl;
        #pragma unroll
        for (int ma = 0; ma < 4; ma++) {
            int r0 = bm + wm*64 + ma*16 + (lane >> 2);
            #pragma unroll
            for (int na = 0; na < 2; na++) {
                int jb = wn*16 + na*8 + 2*(lane & 3);
                #pragma unroll
                for (int half = 0; half < 2; half++) {
                    int r = r0 + half*8;
                    int spos = r & (S_ - 1);
                    float c0 = g_tab[((size_t)jb*S_ + spos)*2];
                    float s0 = g_tab[((size_t)jb*S_ + spos)*2 + 1];
                    float c1 = g_tab[((size_t)(jb+1)*S_ + spos)*2];
                    float s1 = g_tab[((size_t)(jb+1)*S_ + spos)*2 + 1];
                    float x1a = acc[ma][na][half*2+0],   x1b = acc[ma][na][half*2+1];
                    float x2a = acc[ma][na+2][half*2+0], x2b = acc[ma][na+2][half*2+1];
                    float y0 = x1a*c0 - x2a*s0, y1 = x1b*c1 - x2b*s1;   // cols jb, jb+1
                    float z0 = x2a*c0 + x1a*s0, z1 = x2b*c1 + x1b*s1;   // cols jb+64, jb+65
                    uint32_t h0, l0, h1, l1;
                    split2(y0, y1, h0, l0);
                    split2(z0, z1, h1, l1);
                    size_t p = (size_t)r*ncols + bn + jb;
                    *(uint32_t*)&dh[p]      = h0;
                    *(uint32_t*)&dl[p]      = l0;
                    *(uint32_t*)&dh[p + 64] = h1;
                    *(uint32_t*)&dl[p + 64] = l1;
                }
            }
        }
    }
}

// ---------------------------------------------------------------------------
// Flash attention on mma.sync, split-bf16 both GEMMs, register softmax.
// 256 threads / 8 warps; warp w owns query rows [w*16, w*16+16).
// NEW: P stays in registers — the m16n8 C-fragment of S is exactly the
// m16k16 A-fragment layout for PV, so no P smem, no ldmatrix for P.
// ---------------------------------------------------------------------------
#define QSTR 136
#define QH_OFF 0u
#define QL_OFF 34816u
#define KH_OFF 69632u
#define KL_OFF 87040u
#define VH_OFF 104448u
#define VL_OFF 121856u
#define ATT_SMEM 139264u

__global__ __launch_bounds__(256) void attn_mma()
{
    extern __shared__ char dsm[];
    const uint32_t sb = smem_to_u32(dsm);
    const int t = threadIdx.x, lane = t & 31, wid = t >> 5;
    const int qt = 15 - blockIdx.x;          // heavy q-tiles first
    const int h = blockIdx.y, b = blockIdx.z;
    const int kvh = h >> 2;
    const int qbase = qt * 128;
    const int r_in = lane >> 2;              // 0..7
    const int c2 = (lane & 3) * 2;

    // load Q tile (hi+lo)
    {
        const __nv_bfloat16* qh = g_qh + (size_t)(b*S_ + qbase)*2048 + h*128;
        const __nv_bfloat16* ql = g_ql + (size_t)(b*S_ + qbase)*2048 + h*128;
        for (int i = t; i < 2048; i += 256) {
            int r = i >> 4, c = (i & 15) * 8;
            uint32_t d = sb + QH_OFF + (uint32_t)((r*QSTR + c)*2);
            CP16(d, qh + (size_t)r*2048 + c);
            CP16(d + QL_OFF, ql + (size_t)r*2048 + c);
        }
        CP_COMMIT();
    }

    float o[16][4];
    #pragma unroll
    for (int i = 0; i < 16; i++)
        #pragma unroll
        for (int e = 0; e < 4; e++) o[i][e] = 0.f;
    float m_run[2] = {-1e30f, -1e30f}, l_run[2] = {0.f, 0.f};

    const float scale = 0.08838834764831845f;
    const int ntiles = 2*qt + 2;
    for (int kt = 0; kt < ntiles; kt++) {
        const int kbase = kt * 64;
        __syncthreads();   // all warps done reading prev K/V
        for (int i = t; i < 1024; i += 256) {
            int r = i >> 4, c = (i & 15) * 8;
            uint32_t doff = (uint32_t)((r*QSTR + c)*2);
            size_t goff = (size_t)(b*S_ + kbase + r)*512 + kvh*128 + c;
            CP16(sb + KH_OFF + doff, g_kh + goff);
            CP16(sb + KL_OFF + doff, g_kl + goff);
            CP16(sb + VH_OFF + doff, g_vh + goff);
            CP16(sb + VL_OFF + doff, g_vl + goff);
        }
        CP_COMMIT();
        CP_WAIT0();
        __syncthreads();

        // ---- S = Q K^T (3-pass split) ----
        float s[8][4];
        #pragma unroll
        for (int na = 0; na < 8; na++)
            #pragma unroll
            for (int e = 0; e < 4; e++) s[na][e] = 0.f;
        #pragma unroll
        for (int ks = 0; ks < 8; ks++) {
            const int k0 = ks * 16;
            uint32_t ah[4], al[4];
            uint32_t aoff = sb + QH_OFF +
                (uint32_t)(((wid*16 + (lane & 15))*QSTR + k0 + (lane >> 4)*8)*2);
            ldsm_x4(ah, aoff);
            ldsm_x4(al, aoff + (QL_OFF - QH_OFF));
            #pragma unroll
            for (int na = 0; na < 8; na++) {
                uint32_t bh[2], bl[2];
                uint32_t boff = sb + KH_OFF +
                    (uint32_t)(((na*8 + (lane & 7))*QSTR + k0 + ((lane >> 3) & 1)*8)*2);
                ldsm_x2(bh, boff);
                ldsm_x2(bl, boff + (KL_OFF - KH_OFF));
                mma_bf16(s[na], ah, bh);
                mma_bf16(s[na], ah, bl);
                mma_bf16(s[na], al, bh);
            }
        }
        // scale + causal mask
        const bool mm = (kt >= 2*qt);
        #pragma unroll
        for (int na = 0; na < 8; na++)
            #pragma unroll
            for (int e = 0; e < 4; e++) {
                float v = s[na][e] * scale;
                if (mm) {
                    int col = kbase + na*8 + c2 + (e & 1);
                    int row = qbase + wid*16 + r_in + (e >> 1)*8;
                    if (col > row) v = -1e30f;
                }
                s[na][e] = v;
            }
        // row max (2 rows per lane)
        float mt[2] = {-1e30f, -1e30f};
        #pragma unroll
        for (int na = 0; na < 8; na++) {
            mt[0] = fmaxf(mt[0], fmaxf(s[na][0], s[na][1]));
            mt[1] = fmaxf(mt[1], fmaxf(s[na][2], s[na][3]));
        }
        #pragma unroll
        for (int x = 1; x < 4; x <<= 1) {
            mt[0] = fmaxf(mt[0], __shfl_xor_sync(0xFFFFFFFFu, mt[0], x));
            mt[1] = fmaxf(mt[1], __shfl_xor_sync(0xFFFFFFFFu, mt[1], x));
        }
        float mn0 = fmaxf(m_run[0], mt[0]), mn1 = fmaxf(m_run[1], mt[1]);
        float al0 = fexp2((m_run[0] - mn0) * LOG2E);
        float al1 = fexp2((m_run[1] - mn1) * LOG2E);
        m_run[0] = mn0; m_run[1] = mn1;

        // p = exp(s - m); keep P in registers as packed bf16 hi/lo A-fragments.
        // ph01[na] = rows (r, r) cols (8na+c2, +1) ; ph23[na] = rows (r+8, r+8).
        float rs0 = 0.f, rs1 = 0.f;
        uint32_t ph01[8], ph23[8], pl01[8], pl23[8];
        #pragma unroll
        for (int na = 0; na < 8; na++) {
            float p0 = fexp2((s[na][0] - mn0) * LOG2E);
            float p1 = fexp2((s[na][1] - mn0) * LOG2E);
            float p2 = fexp2((s[na][2] - mn1) * LOG2E);
            float p3 = fexp2((s[na][3] - mn1) * LOG2E);
            rs0 += p0 + p1; rs1 += p2 + p3;
            split2(p0, p1, ph01[na], pl01[na]);
            split2(p2, p3, ph23[na], pl23[na]);
        }
        #pragma unroll
        for (int x = 1; x < 4; x <<= 1) {
            rs0 += __shfl_xor_sync(0xFFFFFFFFu, rs0, x);
            rs1 += __shfl_xor_sync(0xFFFFFFFFu, rs1, x);
        }
        l_run[0] = l_run[0]*al0 + rs0;
        l_run[1] = l_run[1]*al1 + rs1;
        // rescale O
        #pragma unroll
        for (int nd = 0; nd < 16; nd++) {
            o[nd][0] *= al0; o[nd][1] *= al0;
            o[nd][2] *= al1; o[nd][3] *= al1;
        }

        // ---- O += P V (3-pass split): P from registers, V via ldmatrix.trans ----
        #pragma unroll
        for (int kk = 0; kk < 4; kk++) {
            const int k0 = kk * 16;
            uint32_t pa_h[4] = { ph01[2*kk], ph23[2*kk], ph01[2*kk+1], ph23[2*kk+1] };
            uint32_t pa_l[4] = { pl01[2*kk], pl23[2*kk], pl01[2*kk+1], pl23[2*kk+1] };
            #pragma unroll
            for (int nd = 0; nd < 16; nd++) {
                uint32_t bh[2], bl[2];
                uint32_t voff = sb + VH_OFF +
                    (uint32_t)(((k0 + (lane & 15))*QSTR + nd*8)*2);
                ldsm_x2_t(bh, voff);
                ldsm_x2_t(bl, voff + (VL_OFF - VH_OFF));
                mma_bf16(o[nd], pa_h, bh);
                mma_bf16(o[nd], pa_l, bh);
                mma_bf16(o[nd], pa_h, bl);
            }
        }
    }

    // ---- epilogue: /= l, emit bf16 hi/lo for out-proj ----
    float inv0 = 1.f / l_run[0], inv1 = 1.f / l_run[1];
    int row0 = b*S_ + qbase + wid*16 + r_in;
    #pragma unroll
    for (int nd = 0; nd < 16; nd++) {
        int d = nd*8 + c2;
        uint32_t h0, l0, h1, l1;
        split2(o[nd][0]*inv0, o[nd][1]*inv0, h0, l0);
        split2(o[nd][2]*inv1, o[nd][3]*inv1, h1, l1);
        size_t p0 = (size_t)row0*2048 + h*128 + d;
        size_t p1 = p0 + (size_t)8*2048;
        *(uint32_t*)&g_ah[p0] = h0;
        *(uint32_t*)&g_al[p0] = l0;
        *(uint32_t*)&g_ah[p1] = h1;
        *(uint32_t*)&g_al[p1] = l1;
    }
}

// ---------------------------------------------------------------------------
// Launch.  Inputs: hidden_states f32, position_ids (arange, unused),
//                  Wq, Wk, Wv, Wo f32.  Output f32 [B,S,H].
// ---------------------------------------------------------------------------
extern "C" void kernel_launch(void* const* d_in, const int* in_sizes, int n_in,
                              void* d_out, int out_size)
{
    (void)in_sizes; (void)n_in; (void)out_size;
    const float* hs = (const float*)d_in[0];
    const float* Wq = (const float*)d_in[2];
    const float* Wk = (const float*)d_in[3];
    const float* Wv = (const float*)d_in[4];
    const float* Wo = (const float*)d_in[5];
    float* out = (float*)d_out;

    cudaFuncSetAttribute(mm_mma, cudaFuncAttributeMaxDynamicSharedMemorySize, MM_SMEM);
    cudaFuncSetAttribute(attn_mma, cudaFuncAttributeMaxDynamicSharedMemorySize, ATT_SMEM);

    // prep
    split_hs_kernel<<<1024, 256>>>(hs);
    wsplit_kernel<<<dim3(2048/32, 2048/32), dim3(32, 8)>>>(Wq, 2048, 2048, 0);
    wsplit_kernel<<<dim3(512/32,  2048/32), dim3(32, 8)>>>(Wk, 2048, 512,  1);
    wsplit_kernel<<<dim3(512/32,  2048/32), dim3(32, 8)>>>(Wv, 2048, 512,  2);
    wsplit_kernel<<<dim3(2048/32, 2048/32), dim3(32, 8)>>>(Wo, 2048, 2048, 3);
    rope_table_kernel<<<(S_*64 + 255)/256, 256>>>();

    // projections (RoPE fused for Q/K; all emit bf16 hi/lo)
    mm_mma<<<dim3(16, 32), 256, MM_SMEM>>>(nullptr, 2048, 0, 0, 1, 2048);
    mm_mma<<<dim3(4,  32), 256, MM_SMEM>>>(nullptr, 2048, 0, 1, 2, 512);
    mm_mma<<<dim3(4,  32), 256, MM_SMEM>>>(nullptr, 2048, 0, 2, 3, 512);

    // attention (tensor-core, split-bf16, register-P)
    attn_mma<<<dim3(16, NH_, B_), 256, ATT_SMEM>>>();

    // output projection
    mm_mma<<<dim3(16, 32), 256, MM_SMEM>>>(out, 2048, 1, 3, 0, 2048);
}